// round 14
// baseline (speedup 1.0000x reference)
#include <cuda_runtime.h>

#define BB 16
#define LL 2048
#define HH 1024
#define ZZ 512

// Scratch (device globals; no allocation allowed)
__device__ float g_k[BB * HH];          // final @ Wk
__device__ float g_kq[BB * HH];         // Wq @ k
__device__ float g_w[BB * LL];          // RAW masked logits (softmax done in k5)
__device__ float g_part[32 * BB * ZZ];  // partial column sums of latent z
__device__ float g_S2[8 * BB * ZZ];     // split-K partials of S (reduced in k5)

// Intra-L1 dependency counters (zero at load; reset by k5 block 0 each run)
__device__ unsigned g_acnt;             // kA blocks done (128)
__device__ unsigned g_bcnt;             // kB blocks done (128)
__device__ unsigned g_zcnt[BB];         // z-sum chunks done per batch (32)

// ---------------------------------------------------------------------------
// L1: all producers, one launch, 512 threads. Block-id order puts the 67 MB
// z-read in wave 1 alongside latency-bound kA; gates only target lower ids.
//   [0,128)      kA
//   [128,640)    z-sum
//   [640,768)    kB      (gate g_acnt==128)
//   [768,896)    kF      (gate g_zcnt[b]==32)
//   [896,1920)   logits  (gate g_bcnt==128)
// ---------------------------------------------------------------------------
__global__ void __launch_bounds__(512) k_prod(
    const float* __restrict__ fin, const float* __restrict__ Wk,
    const float* __restrict__ Wq,  const float* __restrict__ Wv,
    const float* __restrict__ zin, const float* __restrict__ enc,
    const int* __restrict__ mask)
{
    __shared__ __align__(16) float smem[8 * HH];   // 32 KB, aliased per stage
    const int blk = blockIdx.x;
    const int t = threadIdx.x;

    if (blk < 128) {
        // ---------------- kA: k[b,h] = fin[b,:] . Wk[:,h] ----------------
        float* sh  = smem;
        float* red = smem + HH;
        const int b = blk >> 3;
        const int hof = t & 127;
        const int h = ((blk & 7) << 7) + hof;
        const int cs = t >> 7;
        for (int j = t; j < HH; j += 512) sh[j] = fin[b * HH + j];
        __syncthreads();
        float acc = 0.f;
        const float* wcol = Wk + h;
#pragma unroll 8
        for (int c = cs * 256; c < (cs + 1) * 256; ++c)
            acc += sh[c] * wcol[(size_t)c * HH];
        red[t] = acc;
        __syncthreads();
        if (cs == 0) {
            g_k[b * HH + h] = red[hof] + red[128 + hof] + red[256 + hof] + red[384 + hof];
            __threadfence();
        }
        __syncthreads();
        if (t == 0) atomicAdd(&g_acnt, 1u);

    } else if (blk < 640) {
        // ---------------- z-sum: (batch, 64-row chunk), float4 ----------------
        const int e = blk - 128;               // 0..511
        const int b = e >> 5;
        const int chunk = e & 31;
        const int sub = t >> 7;                // 0..3
        const int col4 = t & 127;
        const float4* base = (const float4*)zin
            + ((size_t)b * LL + (size_t)chunk * 64 + sub) * (ZZ / 4) + col4;
        float4 acc = make_float4(0.f, 0.f, 0.f, 0.f);
#pragma unroll
        for (int i = 0; i < 16; ++i) {         // rows sub+4i
            const float4 v = __ldcs(base + (size_t)i * ZZ);
            acc.x += v.x; acc.y += v.y; acc.z += v.z; acc.w += v.w;
        }
        float4* sred = (float4*)smem;          // 3*128 float4
        if (sub > 0) sred[(sub - 1) * 128 + col4] = acc;
        __syncthreads();
        if (sub == 0) {
#pragma unroll
            for (int j = 0; j < 3; ++j) {
                const float4 p = sred[j * 128 + col4];
                acc.x += p.x; acc.y += p.y; acc.z += p.z; acc.w += p.w;
            }
            ((float4*)g_part)[(chunk * BB + b) * (ZZ / 4) + col4] = acc;
            __threadfence();
        }
        __syncthreads();
        if (t == 0) atomicAdd(&g_zcnt[b], 1u);

    } else if (blk < 768) {
        // ---------------- kB batch-shared (gate kA) ----------------
        if (t == 0) {
            while (*(volatile unsigned*)&g_acnt < 128u) {}
            __threadfence();
        }
        __syncthreads();

        float* sk = smem;                      // 8 k-vectors, 32 KB
        const int e = blk - 640;
        const int rb = e >> 1;
        const int bg = e & 1;
        for (int j = t; j < 8 * HH; j += 512)
            sk[j] = __ldcg(&g_k[(8 * bg + (j >> 10)) * HH + (j & 1023)]);
        __syncthreads();

        const int warp = t >> 5, lane = t & 31;
        const int r = rb * 16 + warp;
        const float4* wrow = (const float4*)(Wq + (size_t)r * HH);
        float acc[8] = {0.f, 0.f, 0.f, 0.f, 0.f, 0.f, 0.f, 0.f};
#pragma unroll 2
        for (int c = lane; c < HH / 4; c += 32) {
            const float4 wv = wrow[c];
#pragma unroll
            for (int j = 0; j < 8; ++j) {
                const float4 kv = ((const float4*)(sk + j * HH))[c];
                acc[j] += wv.x * kv.x + wv.y * kv.y + wv.z * kv.z + wv.w * kv.w;
            }
        }
#pragma unroll
        for (int j = 0; j < 8; ++j) {
            float a = acc[j];
#pragma unroll
            for (int o = 16; o; o >>= 1) a += __shfl_xor_sync(0xffffffffu, a, o);
            if (lane == 0) g_kq[(8 * bg + j) * HH + r] = a;
        }
        if (lane == 0) __threadfence();
        __syncthreads();
        if (t == 0) atomicAdd(&g_bcnt, 1u);

    } else if (blk < 896) {
        // ---------------- kF split-K (gate z[b]) ----------------
        const int e = blk - 768;               // 0..127
        const int b = e >> 3;
        const int slice = e & 7;
        if (t == 0) {
            while (*(volatile unsigned*)&g_zcnt[b] < 32u) {}
            __threadfence();
        }
        __syncthreads();

        float* zs = smem;                      // [64]
        const int cl = t >> 3;                 // 0..63
        const int sub = t & 7;                 // 0..7
        const int c = 64 * slice + cl;
        float a = 0.f;
#pragma unroll
        for (int j = 0; j < 4; ++j)
            a += __ldcg(&g_part[((sub + 8 * j) * BB + b) * ZZ + c]);
#pragma unroll
        for (int o = 4; o; o >>= 1) a += __shfl_xor_sync(0xffffffffu, a, o);
        if (sub == 0) zs[cl] = a;
        __syncthreads();

        float s = 0.f;
        const float* wbase = Wv + (size_t)(64 * slice) * ZZ + t;
#pragma unroll 8
        for (int c2 = 0; c2 < 64; ++c2)
            s += zs[c2] * wbase[(size_t)c2 * ZZ];
        g_S2[(slice * BB + b) * ZZ + t] = s;

    } else {
        // ---------------- logits, 2 rows/warp (gate kB) ----------------
        if (t == 0) {
            while (*(volatile unsigned*)&g_bcnt < 128u) {}
            __threadfence();
        }
        __syncthreads();

        const int warp = t >> 5, lane = t & 31;
        const int row = ((blk - 896) * 16 + warp) * 2;
        const int b = row >> 11;
        const float4* e40 = (const float4*)(enc + (size_t)row * HH);
        const float4* e41 = (const float4*)(enc + (size_t)(row + 1) * HH);
        const float4* kq4 = (const float4*)(g_kq + b * HH);
        float acc0 = 0.f, acc1 = 0.f;
#pragma unroll
        for (int c = lane; c < HH / 4; c += 32) {
            const float4 ev0 = __ldcs(&e40[c]);
            const float4 ev1 = __ldcs(&e41[c]);
            const float4 kv = __ldcg(&kq4[c]);
            acc0 += ev0.x * kv.x + ev0.y * kv.y + ev0.z * kv.z + ev0.w * kv.w;
            acc1 += ev1.x * kv.x + ev1.y * kv.y + ev1.z * kv.z + ev1.w * kv.w;
        }
#pragma unroll
        for (int o = 16; o; o >>= 1) {
            acc0 += __shfl_xor_sync(0xffffffffu, acc0, o);
            acc1 += __shfl_xor_sync(0xffffffffu, acc1, o);
        }
        if (lane == 0) {
            float v0 = acc0 * 0.03125f;
            float v1 = acc1 * 0.03125f;
            if (mask[row] == 0)     v0 = -1e9f;
            if (mask[row + 1] == 0) v1 = -1e9f;
            g_w[row]     = v0;
            g_w[row + 1] = v1;
        }
    }
}

// ---------------------------------------------------------------------------
// k5: pure writer (R8 proven form). 5120 blocks x 256 threads, 16 float4/thr.
// Block 0 resets L1 counters for the next graph replay.
// ---------------------------------------------------------------------------
__global__ void __launch_bounds__(256) k5_write(float* __restrict__ out)
{
    __shared__ float red[8];
    __shared__ float s_max, s_inv;
    const int blk = blockIdx.x;
    const int t = threadIdx.x;
    const int warp = t >> 5, lane = t & 31;

    if (blk == 0 && t == 0) {
        g_acnt = 0u;
        g_bcnt = 0u;
#pragma unroll
        for (int i = 0; i < BB; ++i) g_zcnt[i] = 0u;
    }

    const bool is_attn = (blk < 4096);
    const int b = is_attn ? (blk >> 8) : ((blk - 4096) >> 6);

    // ---- softmax stats over this batch's 2048 raw logits ----
    float lg[8];
#pragma unroll
    for (int k = 0; k < 8; ++k) lg[k] = __ldg(&g_w[b * LL + k * 256 + t]);

    float m = lg[0];
#pragma unroll
    for (int k = 1; k < 8; ++k) m = fmaxf(m, lg[k]);
#pragma unroll
    for (int o = 16; o; o >>= 1) m = fmaxf(m, __shfl_xor_sync(0xffffffffu, m, o));
    if (lane == 0) red[warp] = m;
    __syncthreads();
    if (warp == 0 && lane < 8) {
        float v = red[lane];
#pragma unroll
        for (int o = 4; o; o >>= 1) v = fmaxf(v, __shfl_xor_sync(0xffu, v, o));
        if (lane == 0) s_max = v;
    }
    __syncthreads();
    const float M = s_max;

    float s = 0.f;
#pragma unroll
    for (int k = 0; k < 8; ++k) s += __expf(lg[k] - M);   // masked rows -> 0
#pragma unroll
    for (int o = 16; o; o >>= 1) s += __shfl_xor_sync(0xffffffffu, s, o);
    __syncthreads();
    if (lane == 0) red[warp] = s;
    __syncthreads();
    if (warp == 0 && lane < 8) {
        float v = red[lane];
#pragma unroll
        for (int o = 4; o; o >>= 1) v += __shfl_xor_sync(0xffu, v, o);
        if (lane == 0) s_inv = 1.f / v;
    }
    __syncthreads();
    const float inv = s_inv;

    // ---- 16 streaming float4 stores per thread ----
    if (is_attn) {
        const long long base = (long long)b * (LL * LL / 4)
                             + (long long)(blk & 255) * 4096;
        const int rowbase = (int)(base >> 9);
        float4* attn4 = (float4*)(out + (size_t)BB * LL * ZZ);
        float w8[8];
#pragma unroll
        for (int j = 0; j < 8; ++j)
            w8[j] = __expf(__ldg(&g_w[rowbase + j]) - M) * inv;
#pragma unroll
        for (int k = 0; k < 16; ++k) {
            const float wv = w8[k >> 1];
            __stcs(attn4 + base + k * 256 + t, make_float4(wv, wv, wv, wv));
        }
    } else {
        const int e = blk - 4096;
        const long long base = (long long)b * (LL * ZZ / 4)
                             + (long long)(e & 63) * 4096;
        const int rowbase = (int)(base >> 7);
        const int rsub = t >> 7;
        const int col = t & 127;
        const float4* S24 = (const float4*)g_S2;
        float4 sv = make_float4(0.f, 0.f, 0.f, 0.f);
#pragma unroll
        for (int k = 0; k < 8; ++k) {
            const float4 p = __ldg(&S24[(k * BB + b) * (ZZ / 4) + col]);
            sv.x += p.x; sv.y += p.y; sv.z += p.z; sv.w += p.w;
        }
#pragma unroll
        for (int k = 0; k < 16; ++k) {
            const float wv = __expf(__ldg(&g_w[rowbase + 2 * k + rsub]) - M) * inv;
            __stcs((float4*)out + base + k * 256 + t,
                   make_float4(wv * sv.x, wv * sv.y, wv * sv.z, wv * sv.w));
        }
    }
}

// ---------------------------------------------------------------------------
extern "C" void kernel_launch(void* const* d_in, const int* in_sizes, int n_in,
                              void* d_out, int out_size)
{
    const float* enc  = (const float*)d_in[0];
    const float* fin  = (const float*)d_in[1];
    const float* zseq = (const float*)d_in[2];
    const int*   mask = (const int*)  d_in[3];
    const float* Wq   = (const float*)d_in[4];
    const float* Wk   = (const float*)d_in[5];
    const float* Wv   = (const float*)d_in[6];
    float* out = (float*)d_out;

    k_prod<<<1920, 512>>>(fin, Wk, Wq, Wv, zseq, enc, mask);
    k5_write<<<5120, 256>>>(out);
}

// round 15
// speedup vs baseline: 1.0927x; 1.0927x over previous
#include <cuda_runtime.h>

#define BB 16
#define LL 2048
#define HH 1024
#define ZZ 512

// Scratch (device globals; no allocation allowed)
__device__ float g_k[BB * HH];          // final @ Wk
__device__ float g_kq[BB * HH];         // Wq @ k
__device__ float g_w[BB * LL];          // RAW masked logits (softmax done in k5)
__device__ float g_part[32 * BB * ZZ];  // partial column sums of latent z
__device__ float g_S2[8 * BB * ZZ];     // split-K partials of S

// Intra-k5 dependency counters (zero at load; reset by k1 each run)
__device__ unsigned g_zcnt[BB];         // z-sum chunks done per batch (32)
__device__ unsigned g_fcnt[BB];         // kF slices done per batch (8)

// ---------------------------------------------------------------------------
// k1: kA batch-shared. 64 blocks = 16 h-chunks x 4 batch-groups, 512 threads.
// Block holds 4 fin vectors in smem; thread (c-slice, h-offset) accumulates
// 4 batches at once; c-slices reduced in smem. Wk L2 traffic: 16 MB total.
// ---------------------------------------------------------------------------
__global__ void __launch_bounds__(512) k1_a(
    const float* __restrict__ fin, const float* __restrict__ Wk)
{
    __shared__ float sfin[4 * HH];          // 16 KB
    __shared__ float sred[7 * 256];         // 7 c-slices x 4 batches x 64 h
    const int blk = blockIdx.x;
    const int t = threadIdx.x;

    if (blk == 0 && t == 0) {
#pragma unroll
        for (int i = 0; i < BB; ++i) { g_zcnt[i] = 0u; g_fcnt[i] = 0u; }
    }

    const int bg = blk & 3;                 // batches 4bg..4bg+3
    const int hc = blk >> 2;                // 0..15, 64 h each
    for (int j = t; j < 4 * HH; j += 512)
        sfin[j] = fin[(4 * bg + (j >> 10)) * HH + (j & 1023)];
    __syncthreads();

    const int ho = t & 63;
    const int cs = t >> 6;                  // 0..7, 128 c each
    const int h = hc * 64 + ho;
    float acc0 = 0.f, acc1 = 0.f, acc2 = 0.f, acc3 = 0.f;
    const float* wcol = Wk + h;
#pragma unroll 8
    for (int c = cs * 128; c < (cs + 1) * 128; ++c) {
        const float w = __ldg(&wcol[(size_t)c * HH]);
        acc0 += w * sfin[c];
        acc1 += w * sfin[HH + c];
        acc2 += w * sfin[2 * HH + c];
        acc3 += w * sfin[3 * HH + c];
    }
    if (cs > 0) {
        float* d = sred + (cs - 1) * 256 + ho;
        d[0] = acc0; d[64] = acc1; d[128] = acc2; d[192] = acc3;
    }
    __syncthreads();
    if (cs == 0) {
#pragma unroll
        for (int s = 0; s < 7; ++s) {
            const float* d = sred + s * 256 + ho;
            acc0 += d[0]; acc1 += d[64]; acc2 += d[128]; acc3 += d[192];
        }
        g_k[(4 * bg + 0) * HH + h] = acc0;
        g_k[(4 * bg + 1) * HH + h] = acc1;
        g_k[(4 * bg + 2) * HH + h] = acc2;
        g_k[(4 * bg + 3) * HH + h] = acc3;
    }
}

// ---------------------------------------------------------------------------
// k2: kB batch-shared, re-gridded. 256 blocks = 64 row-blocks x 4 batch-groups.
// Block holds 4 k-vectors in smem; warp per row, 4 batch accumulators.
// ---------------------------------------------------------------------------
__global__ void __launch_bounds__(512) k2_b(const float* __restrict__ Wq)
{
    __shared__ __align__(16) float sk[4 * HH];      // 16 KB
    const int blk = blockIdx.x;
    const int t = threadIdx.x;
    const int rb = blk >> 2;                // 0..63, 16 rows each
    const int bg = blk & 3;                 // batches 4bg..4bg+3
    for (int j = t; j < 4 * HH; j += 512)
        sk[j] = g_k[(4 * bg + (j >> 10)) * HH + (j & 1023)];
    __syncthreads();

    const int warp = t >> 5, lane = t & 31;
    const int r = rb * 16 + warp;
    const float4* wrow = (const float4*)(Wq + (size_t)r * HH);
    const float4* sk4 = (const float4*)sk;
    float acc[4] = {0.f, 0.f, 0.f, 0.f};
#pragma unroll
    for (int c = lane; c < HH / 4; c += 32) {
        const float4 wv = wrow[c];
#pragma unroll
        for (int j = 0; j < 4; ++j) {
            const float4 kv = sk4[j * (HH / 4) + c];
            acc[j] += wv.x * kv.x + wv.y * kv.y + wv.z * kv.z + wv.w * kv.w;
        }
    }
#pragma unroll
    for (int j = 0; j < 4; ++j) {
        float a = acc[j];
#pragma unroll
        for (int o = 16; o; o >>= 1) a += __shfl_xor_sync(0xffffffffu, a, o);
        if (lane == 0) g_kq[(4 * bg + j) * HH + r] = a;
    }
}

// ---------------------------------------------------------------------------
// k3: pure logits, 2 rows per warp. 1024 blocks x 512 threads.
// ---------------------------------------------------------------------------
__global__ void __launch_bounds__(512) k3_logits(
    const float* __restrict__ enc, const int* __restrict__ mask)
{
    const int warp = threadIdx.x >> 5, lane = threadIdx.x & 31;
    const int row = (blockIdx.x * 16 + warp) * 2;
    const int b = row >> 11;
    const float4* e40 = (const float4*)(enc + (size_t)row * HH);
    const float4* e41 = (const float4*)(enc + (size_t)(row + 1) * HH);
    const float4* kq4 = (const float4*)(g_kq + b * HH);
    float acc0 = 0.f, acc1 = 0.f;
#pragma unroll
    for (int c = lane; c < HH / 4; c += 32) {
        const float4 ev0 = __ldcs(&e40[c]);
        const float4 ev1 = __ldcs(&e41[c]);
        const float4 kv = __ldg(&kq4[c]);
        acc0 += ev0.x * kv.x + ev0.y * kv.y + ev0.z * kv.z + ev0.w * kv.w;
        acc1 += ev1.x * kv.x + ev1.y * kv.y + ev1.z * kv.z + ev1.w * kv.w;
    }
#pragma unroll
    for (int o = 16; o; o >>= 1) {
        acc0 += __shfl_xor_sync(0xffffffffu, acc0, o);
        acc1 += __shfl_xor_sync(0xffffffffu, acc1, o);
    }
    if (lane == 0) {
        float v0 = acc0 * 0.03125f;
        float v1 = acc1 * 0.03125f;
        if (mask[row] == 0)     v0 = -1e9f;
        if (mask[row + 1] == 0) v1 = -1e9f;
        g_w[row]     = v0;
        g_w[row + 1] = v1;
    }
}

// ---------------------------------------------------------------------------
// k5: z-sum + kF + softmax + writers, ONE launch (R13 proven, 60us @72% DRAM).
// 5760 blocks x 256 threads.
//   [0,512)      z-sum   [512,640) kF (gate z[b])
//   [640,4736)   attn writers (no gate)   [4736,5760) out writers (gate kF[b])
// ---------------------------------------------------------------------------
__global__ void __launch_bounds__(256) k5_fused(
    const float* __restrict__ zin, const float* __restrict__ Wv,
    float* __restrict__ out)
{
    __shared__ __align__(16) float smem[640];
    __shared__ float red[8];
    __shared__ float s_max, s_inv;
    const int blk = blockIdx.x;
    const int t = threadIdx.x;

    if (blk < 512) {
        const int b = blk >> 5;
        const int chunk = blk & 31;
        const int sub = t >> 7;
        const int col4 = t & 127;
        const float4* base = (const float4*)zin
            + ((size_t)b * LL + (size_t)chunk * 64 + sub) * (ZZ / 4) + col4;
        float4 acc = make_float4(0.f, 0.f, 0.f, 0.f);
#pragma unroll
        for (int i = 0; i < 32; ++i) {
            const float4 v = __ldcs(base + (size_t)i * 2 * (ZZ / 4));
            acc.x += v.x; acc.y += v.y; acc.z += v.z; acc.w += v.w;
        }
        float4* sred = (float4*)smem;
        if (sub == 1) sred[col4] = acc;
        __syncthreads();
        if (sub == 0) {
            const float4 p = sred[col4];
            acc.x += p.x; acc.y += p.y; acc.z += p.z; acc.w += p.w;
            ((float4*)g_part)[(chunk * BB + b) * (ZZ / 4) + col4] = acc;
        }
        __threadfence();
        __syncthreads();
        if (t == 0) atomicAdd(&g_zcnt[b], 1u);

    } else if (blk < 640) {
        const int e = blk - 512;
        const int b = e >> 3;
        const int slice = e & 7;
        if (t == 0) {
            while (*(volatile unsigned*)&g_zcnt[b] < 32u) {}
            __threadfence();
        }
        __syncthreads();

        float* zs = smem;
        const int cl = t >> 2;
        const int sub = t & 3;
        const int c = 64 * slice + cl;
        float a = 0.f;
#pragma unroll
        for (int j = 0; j < 8; ++j)
            a += __ldcg(&g_part[((sub + 4 * j) * BB + b) * ZZ + c]);
#pragma unroll
        for (int o = 2; o; o >>= 1) a += __shfl_xor_sync(0xffffffffu, a, o);
        if (sub == 0) zs[cl] = a;
        __syncthreads();

#pragma unroll
        for (int h = 0; h < 2; ++h) {
            const int tt = t + 256 * h;
            float s = 0.f;
            const float* wbase = Wv + (size_t)(64 * slice) * ZZ + tt;
#pragma unroll 8
            for (int c2 = 0; c2 < 64; ++c2)
                s += zs[c2] * wbase[(size_t)c2 * ZZ];
            g_S2[(slice * BB + b) * ZZ + tt] = s;
        }
        __threadfence();
        __syncthreads();
        if (t == 0) atomicAdd(&g_fcnt[b], 1u);

    } else {
        const bool is_attn = (blk < 4736);
        const int wb = is_attn ? (blk - 640) : (blk - 4736);
        const int b = is_attn ? (wb >> 8) : (wb >> 6);

        if (!is_attn && t == 0) {
            while (*(volatile unsigned*)&g_fcnt[b] < 8u) {}
            __threadfence();
        }
        __syncthreads();

        const int warp = t >> 5, lane = t & 31;
        float lg[8];
#pragma unroll
        for (int k = 0; k < 8; ++k) lg[k] = __ldg(&g_w[b * LL + k * 256 + t]);

        float m = lg[0];
#pragma unroll
        for (int k = 1; k < 8; ++k) m = fmaxf(m, lg[k]);
#pragma unroll
        for (int o = 16; o; o >>= 1) m = fmaxf(m, __shfl_xor_sync(0xffffffffu, m, o));
        if (lane == 0) red[warp] = m;
        __syncthreads();
        if (warp == 0 && lane < 8) {
            float v = red[lane];
#pragma unroll
            for (int o = 4; o; o >>= 1) v = fmaxf(v, __shfl_xor_sync(0xffu, v, o));
            if (lane == 0) s_max = v;
        }
        __syncthreads();
        const float M = s_max;

        float s = 0.f;
#pragma unroll
        for (int k = 0; k < 8; ++k) s += __expf(lg[k] - M);
#pragma unroll
        for (int o = 16; o; o >>= 1) s += __shfl_xor_sync(0xffffffffu, s, o);
        __syncthreads();
        if (lane == 0) red[warp] = s;
        __syncthreads();
        if (warp == 0 && lane < 8) {
            float v = red[lane];
#pragma unroll
            for (int o = 4; o; o >>= 1) v += __shfl_xor_sync(0xffu, v, o);
            if (lane == 0) s_inv = 1.f / v;
        }
        __syncthreads();
        const float inv = s_inv;

        if (is_attn) {
            const long long base = (long long)b * (LL * LL / 4)
                                 + (long long)(wb & 255) * 4096;
            const int rowbase = (int)(base >> 9);
            float4* attn4 = (float4*)(out + (size_t)BB * LL * ZZ);
            float w8[8];
#pragma unroll
            for (int j = 0; j < 8; ++j)
                w8[j] = __expf(__ldg(&g_w[rowbase + j]) - M) * inv;
#pragma unroll
            for (int k = 0; k < 16; ++k) {
                const float wv = w8[k >> 1];
                __stcs(attn4 + base + k * 256 + t, make_float4(wv, wv, wv, wv));
            }
        } else {
            const long long base = (long long)b * (LL * ZZ / 4)
                                 + (long long)(wb & 63) * 4096;
            const int rowbase = (int)(base >> 7);
            const int rsub = t >> 7;
            const int col = t & 127;
            const float4* S24 = (const float4*)g_S2;
            float4 sv = make_float4(0.f, 0.f, 0.f, 0.f);
#pragma unroll
            for (int k = 0; k < 8; ++k) {
                const float4 p = __ldcg(&S24[(k * BB + b) * (ZZ / 4) + col]);
                sv.x += p.x; sv.y += p.y; sv.z += p.z; sv.w += p.w;
            }
#pragma unroll
            for (int k = 0; k < 16; ++k) {
                const float wv = __expf(__ldg(&g_w[rowbase + 2 * k + rsub]) - M) * inv;
                __stcs((float4*)out + base + k * 256 + t,
                       make_float4(wv * sv.x, wv * sv.y, wv * sv.z, wv * sv.w));
            }
        }
    }
}

// ---------------------------------------------------------------------------
extern "C" void kernel_launch(void* const* d_in, const int* in_sizes, int n_in,
                              void* d_out, int out_size)
{
    const float* enc  = (const float*)d_in[0];
    const float* fin  = (const float*)d_in[1];
    const float* zseq = (const float*)d_in[2];
    const int*   mask = (const int*)  d_in[3];
    const float* Wq   = (const float*)d_in[4];
    const float* Wk   = (const float*)d_in[5];
    const float* Wv   = (const float*)d_in[6];
    float* out = (float*)d_out;

    k1_a<<<64, 512>>>(fin, Wk);               // kA batch-shared (+ counter reset)
    k2_b<<<256, 512>>>(Wq);                   // kB batch-shared, 256 blocks
    k3_logits<<<1024, 512>>>(enc, mask);      // logits (2 rows/warp)
    k5_fused<<<5760, 256>>>(zseq, Wv, out);   // z-sum + kF + softmax + writers
}

// round 16
// speedup vs baseline: 1.1632x; 1.0645x over previous
#include <cuda_runtime.h>

#define BB 16
#define LL 2048
#define HH 1024
#define ZZ 512

// Scratch (device globals; no allocation allowed)
__device__ float g_k[BB * HH];          // final @ Wk
__device__ float g_kq[BB * HH];         // Wq @ k
__device__ float g_w[BB * LL];          // RAW masked logits (softmax done in k5)
__device__ float g_part[32 * BB * ZZ];  // partial column sums of latent z
__device__ float g_S2[8 * BB * ZZ];     // split-K partials of S

// Dependency counters (zero at load; reset by k12 block 0 each run)
__device__ unsigned g_acnt;             // kA blocks done (128)
__device__ unsigned g_zcnt[BB];         // z-sum chunks done per batch (32)
__device__ unsigned g_fcnt[BB];         // kF slices done per batch (8)

// ---------------------------------------------------------------------------
// k12: kA + kB in ONE launch (all 384 blocks co-resident in wave 1; the only
// gate is kB<-kA with nothing else to displace).
//   [0,128)    kA batch-shared: 16 h-chunks x 8 batch-groups (2 batches each)
//   [128,384)  kB batch-shared: 64 row-blocks x 4 batch-groups (gate g_acnt)
// ---------------------------------------------------------------------------
__global__ void __launch_bounds__(512) k12_weights(
    const float* __restrict__ fin, const float* __restrict__ Wk,
    const float* __restrict__ Wq)
{
    __shared__ __align__(16) float smem[4 * HH];    // 16 KB (kA: fin2 + red)
    const int blk = blockIdx.x;
    const int t = threadIdx.x;

    if (blk == 0 && t == 0) {
#pragma unroll
        for (int i = 0; i < BB; ++i) { g_zcnt[i] = 0u; g_fcnt[i] = 0u; }
    }

    if (blk < 128) {
        // ---- kA: k[b,h] = fin[b,:] . Wk[:,h], 2 batches per block ----
        float* sfin = smem;                 // [2*HH]
        float* sred = smem + 2 * HH;        // 7 c-slices x 2 batches x 64 h... need 7*128
        const int bg = blk & 7;             // batches 2bg, 2bg+1
        const int hc = blk >> 3;            // 0..15, 64 h each
        for (int j = t; j < 2 * HH; j += 512)
            sfin[j] = fin[(2 * bg + (j >> 10)) * HH + (j & 1023)];
        __syncthreads();

        const int ho = t & 63;
        const int cs = t >> 6;              // 0..7, 128 c each
        const int h = hc * 64 + ho;
        float acc0 = 0.f, acc1 = 0.f;
        const float* wcol = Wk + h;
#pragma unroll 8
        for (int c = cs * 128; c < (cs + 1) * 128; ++c) {
            const float w = __ldg(&wcol[(size_t)c * HH]);
            acc0 += w * sfin[c];
            acc1 += w * sfin[HH + c];
        }
        if (cs > 0) {
            float* d = sred + (cs - 1) * 128 + ho;
            d[0] = acc0; d[64] = acc1;
        }
        __syncthreads();
        if (cs == 0) {
#pragma unroll
            for (int s = 0; s < 7; ++s) {
                const float* d = sred + s * 128 + ho;
                acc0 += d[0]; acc1 += d[64];
            }
            g_k[(2 * bg + 0) * HH + h] = acc0;
            g_k[(2 * bg + 1) * HH + h] = acc1;
            __threadfence();
        }
        __syncthreads();
        if (t == 0) atomicAdd(&g_acnt, 1u);

    } else {
        // ---- kB: kq[b,r] = Wq[r,:] . k[b,:], 4 batches per block (gate kA) ----
        if (t == 0) {
            while (*(volatile unsigned*)&g_acnt < 128u) {}
            __threadfence();
        }
        __syncthreads();

        float* sk = smem;                   // 4 k-vectors, 16 KB
        const int e = blk - 128;
        const int rb = e >> 2;              // 0..63, 16 rows each
        const int bg = e & 3;               // batches 4bg..4bg+3
        for (int j = t; j < 4 * HH; j += 512)
            sk[j] = __ldcg(&g_k[(4 * bg + (j >> 10)) * HH + (j & 1023)]);
        __syncthreads();

        const int warp = t >> 5, lane = t & 31;
        const int r = rb * 16 + warp;
        const float4* wrow = (const float4*)(Wq + (size_t)r * HH);
        const float4* sk4 = (const float4*)sk;
        float acc[4] = {0.f, 0.f, 0.f, 0.f};
#pragma unroll
        for (int c = lane; c < HH / 4; c += 32) {
            const float4 wv = wrow[c];
#pragma unroll
            for (int j = 0; j < 4; ++j) {
                const float4 kv = sk4[j * (HH / 4) + c];
                acc[j] += wv.x * kv.x + wv.y * kv.y + wv.z * kv.z + wv.w * kv.w;
            }
        }
#pragma unroll
        for (int j = 0; j < 4; ++j) {
            float a = acc[j];
#pragma unroll
            for (int o = 16; o; o >>= 1) a += __shfl_xor_sync(0xffffffffu, a, o);
            if (lane == 0) g_kq[(4 * bg + j) * HH + r] = a;
        }
    }
}

// ---------------------------------------------------------------------------
// k3: pure logits, 2 rows per warp. 1024 blocks x 512 threads. (at enc floor)
// ---------------------------------------------------------------------------
__global__ void __launch_bounds__(512) k3_logits(
    const float* __restrict__ enc, const int* __restrict__ mask)
{
    const int warp = threadIdx.x >> 5, lane = threadIdx.x & 31;
    const int row = (blockIdx.x * 16 + warp) * 2;
    const int b = row >> 11;
    const float4* e40 = (const float4*)(enc + (size_t)row * HH);
    const float4* e41 = (const float4*)(enc + (size_t)(row + 1) * HH);
    const float4* kq4 = (const float4*)(g_kq + b * HH);
    float acc0 = 0.f, acc1 = 0.f;
#pragma unroll
    for (int c = lane; c < HH / 4; c += 32) {
        const float4 ev0 = __ldcs(&e40[c]);
        const float4 ev1 = __ldcs(&e41[c]);
        const float4 kv = __ldg(&kq4[c]);
        acc0 += ev0.x * kv.x + ev0.y * kv.y + ev0.z * kv.z + ev0.w * kv.w;
        acc1 += ev1.x * kv.x + ev1.y * kv.y + ev1.z * kv.z + ev1.w * kv.w;
    }
#pragma unroll
    for (int o = 16; o; o >>= 1) {
        acc0 += __shfl_xor_sync(0xffffffffu, acc0, o);
        acc1 += __shfl_xor_sync(0xffffffffu, acc1, o);
    }
    if (lane == 0) {
        float v0 = acc0 * 0.03125f;
        float v1 = acc1 * 0.03125f;
        if (mask[row] == 0)     v0 = -1e9f;
        if (mask[row + 1] == 0) v1 = -1e9f;
        g_w[row]     = v0;
        g_w[row + 1] = v1;
    }
}

// ---------------------------------------------------------------------------
// k5: z-sum + kF + softmax + writers, ONE launch (proven 61.5us @70% DRAM).
// 5760 blocks x 256 threads.
//   [0,512)      z-sum   [512,640) kF (gate z[b])
//   [640,4736)   attn writers (no gate)   [4736,5760) out writers (gate kF[b])
// ---------------------------------------------------------------------------
__global__ void __launch_bounds__(256) k5_fused(
    const float* __restrict__ zin, const float* __restrict__ Wv,
    float* __restrict__ out)
{
    __shared__ __align__(16) float smem[640];
    __shared__ float red[8];
    __shared__ float s_max, s_inv;
    const int blk = blockIdx.x;
    const int t = threadIdx.x;

    if (blk < 512) {
        const int b = blk >> 5;
        const int chunk = blk & 31;
        const int sub = t >> 7;
        const int col4 = t & 127;
        const float4* base = (const float4*)zin
            + ((size_t)b * LL + (size_t)chunk * 64 + sub) * (ZZ / 4) + col4;
        float4 acc = make_float4(0.f, 0.f, 0.f, 0.f);
#pragma unroll
        for (int i = 0; i < 32; ++i) {
            const float4 v = __ldcs(base + (size_t)i * 2 * (ZZ / 4));
            acc.x += v.x; acc.y += v.y; acc.z += v.z; acc.w += v.w;
        }
        float4* sred = (float4*)smem;
        if (sub == 1) sred[col4] = acc;
        __syncthreads();
        if (sub == 0) {
            const float4 p = sred[col4];
            acc.x += p.x; acc.y += p.y; acc.z += p.z; acc.w += p.w;
            ((float4*)g_part)[(chunk * BB + b) * (ZZ / 4) + col4] = acc;
        }
        __threadfence();
        __syncthreads();
        if (t == 0) atomicAdd(&g_zcnt[b], 1u);

    } else if (blk < 640) {
        const int e = blk - 512;
        const int b = e >> 3;
        const int slice = e & 7;
        if (t == 0) {
            while (*(volatile unsigned*)&g_zcnt[b] < 32u) {}
            __threadfence();
        }
        __syncthreads();

        float* zs = smem;
        const int cl = t >> 2;
        const int sub = t & 3;
        const int c = 64 * slice + cl;
        float a = 0.f;
#pragma unroll
        for (int j = 0; j < 8; ++j)
            a += __ldcg(&g_part[((sub + 4 * j) * BB + b) * ZZ + c]);
#pragma unroll
        for (int o = 2; o; o >>= 1) a += __shfl_xor_sync(0xffffffffu, a, o);
        if (sub == 0) zs[cl] = a;
        __syncthreads();

#pragma unroll
        for (int h = 0; h < 2; ++h) {
            const int tt = t + 256 * h;
            float s = 0.f;
            const float* wbase = Wv + (size_t)(64 * slice) * ZZ + tt;
#pragma unroll 8
            for (int c2 = 0; c2 < 64; ++c2)
                s += zs[c2] * wbase[(size_t)c2 * ZZ];
            g_S2[(slice * BB + b) * ZZ + tt] = s;
        }
        __threadfence();
        __syncthreads();
        if (t == 0) atomicAdd(&g_fcnt[b], 1u);

    } else {
        const bool is_attn = (blk < 4736);
        const int wb = is_attn ? (blk - 640) : (blk - 4736);
        const int b = is_attn ? (wb >> 8) : (wb >> 6);

        if (!is_attn && t == 0) {
            while (*(volatile unsigned*)&g_fcnt[b] < 8u) {}
            __threadfence();
        }
        __syncthreads();

        const int warp = t >> 5, lane = t & 31;
        float lg[8];
#pragma unroll
        for (int k = 0; k < 8; ++k) lg[k] = __ldg(&g_w[b * LL + k * 256 + t]);

        float m = lg[0];
#pragma unroll
        for (int k = 1; k < 8; ++k) m = fmaxf(m, lg[k]);
#pragma unroll
        for (int o = 16; o; o >>= 1) m = fmaxf(m, __shfl_xor_sync(0xffffffffu, m, o));
        if (lane == 0) red[warp] = m;
        __syncthreads();
        if (warp == 0 && lane < 8) {
            float v = red[lane];
#pragma unroll
            for (int o = 4; o; o >>= 1) v = fmaxf(v, __shfl_xor_sync(0xffu, v, o));
            if (lane == 0) s_max = v;
        }
        __syncthreads();
        const float M = s_max;

        float s = 0.f;
#pragma unroll
        for (int k = 0; k < 8; ++k) s += __expf(lg[k] - M);
#pragma unroll
        for (int o = 16; o; o >>= 1) s += __shfl_xor_sync(0xffffffffu, s, o);
        __syncthreads();
        if (lane == 0) red[warp] = s;
        __syncthreads();
        if (warp == 0 && lane < 8) {
            float v = red[lane];
#pragma unroll
            for (int o = 4; o; o >>= 1) v += __shfl_xor_sync(0xffu, v, o);
            if (lane == 0) s_inv = 1.f / v;
        }
        __syncthreads();
        const float inv = s_inv;

        if (is_attn) {
            const long long base = (long long)b * (LL * LL / 4)
                                 + (long long)(wb & 255) * 4096;
            const int rowbase = (int)(base >> 9);
            float4* attn4 = (float4*)(out + (size_t)BB * LL * ZZ);
            float w8[8];
#pragma unroll
            for (int j = 0; j < 8; ++j)
                w8[j] = __expf(__ldg(&g_w[rowbase + j]) - M) * inv;
#pragma unroll
            for (int k = 0; k < 16; ++k) {
                const float wv = w8[k >> 1];
                __stcs(attn4 + base + k * 256 + t, make_float4(wv, wv, wv, wv));
            }
        } else {
            const long long base = (long long)b * (LL * ZZ / 4)
                                 + (long long)(wb & 63) * 4096;
            const int rowbase = (int)(base >> 7);
            const int rsub = t >> 7;
            const int col = t & 127;
            const float4* S24 = (const float4*)g_S2;
            float4 sv = make_float4(0.f, 0.f, 0.f, 0.f);
#pragma unroll
            for (int k = 0; k < 8; ++k) {
                const float4 p = __ldcg(&S24[(k * BB + b) * (ZZ / 4) + col]);
                sv.x += p.x; sv.y += p.y; sv.z += p.z; sv.w += p.w;
            }
#pragma unroll
            for (int k = 0; k < 16; ++k) {
                const float wv = __expf(__ldg(&g_w[rowbase + 2 * k + rsub]) - M) * inv;
                __stcs((float4*)out + base + k * 256 + t,
                       make_float4(wv * sv.x, wv * sv.y, wv * sv.z, wv * sv.w));
            }
        }
    }
}

// ---------------------------------------------------------------------------
extern "C" void kernel_launch(void* const* d_in, const int* in_sizes, int n_in,
                              void* d_out, int out_size)
{
    const float* enc  = (const float*)d_in[0];
    const float* fin  = (const float*)d_in[1];
    const float* zseq = (const float*)d_in[2];
    const int*   mask = (const int*)  d_in[3];
    const float* Wq   = (const float*)d_in[4];
    const float* Wk   = (const float*)d_in[5];
    const float* Wv   = (const float*)d_in[6];
    float* out = (float*)d_out;

    k12_weights<<<384, 512>>>(fin, Wk, Wq);   // kA + kB fused (+ counter reset)
    k3_logits<<<1024, 512>>>(enc, mask);      // logits (2 rows/warp)
    k5_fused<<<5760, 256>>>(zseq, Wv, out);   // z-sum + kF + softmax + writers
}